// round 1
// baseline (speedup 1.0000x reference)
#include <cuda_runtime.h>
#include <math.h>

// ---------------------------------------------------------------------------
// TransformerBlock: out = x + attn(x) + mlp(x)
//   attn: scores = (x@qk)@x^T, causal softmax, attn = (P@x)@ov
//   mlp:  relu(relu(relu(x@w_up^T+b_up)@w_hidden^T+b_hid)@w_down^T+b_down)
// Shapes: x[4096,2048] qk,ov[2048,2048] w_up[8192,2048] w_hidden[8192,8192]
//         w_down[2048,8192]
// ---------------------------------------------------------------------------

#define N_CTX    4096
#define D_MODEL  2048
#define D_HIDDEN 8192

#define BM 128
#define BN 128
#define BK 8
#define PAD 4

// Scratch (static device allocations are the sanctioned workaround)
__device__ float g_tmp1[(size_t)N_CTX * D_MODEL];    // x@qk
__device__ float g_scores[(size_t)N_CTX * N_CTX];    // scores / probs (in-place)
__device__ float g_tmp2[(size_t)N_CTX * D_MODEL];    // P@x
__device__ float g_attn[(size_t)N_CTX * D_MODEL];    // (P@x)@ov
__device__ float g_a1[(size_t)N_CTX * D_HIDDEN];
__device__ float g_a2[(size_t)N_CTX * D_HIDDEN];

// EPI: 0 = plain store, 1 = relu(acc+bias), 2 = add1 + add2 + relu(acc+bias)
template <bool TRANSB, int EPI>
__global__ __launch_bounds__(256) void gemm_kernel(
    const float* __restrict__ A,   // [M,K] row-major
    const float* __restrict__ B,   // NN: [K,N] ; NT: [N,K]
    float* __restrict__ C,         // [M,N]
    int M, int N, int K,
    const float* __restrict__ bias,   // [N] (EPI>=1)
    const float* __restrict__ add1,   // [M,N] (EPI==2)
    const float* __restrict__ add2)   // [M,N] (EPI==2)
{
    __shared__ float As[BK][BM + PAD];
    __shared__ float Bs[BK][BN + PAD];

    const int tid = threadIdx.x;
    const int tx  = tid & 15;          // 0..15 -> n frag
    const int ty  = tid >> 4;          // 0..15 -> m frag
    const int m0  = blockIdx.y * BM;
    const int n0  = blockIdx.x * BN;

    // A tile loader: 128 rows x 8 cols = 256 float4, 1 per thread
    const int a_m  = tid >> 1;
    const int a_k4 = (tid & 1) * 4;
    // B tile loader
    const int bt_n  = tid >> 1;          // TRANSB: row in B' (n), 2 f4 rows? no: 1 f4
    const int bt_k4 = (tid & 1) * 4;
    const int bn_k  = tid >> 5;          // NN: k row
    const int bn_n4 = (tid & 31) * 4;    // NN: n col

    float acc[8][8];
#pragma unroll
    for (int i = 0; i < 8; ++i)
#pragma unroll
        for (int j = 0; j < 8; ++j) acc[i][j] = 0.f;

    for (int k0 = 0; k0 < K; k0 += BK) {
        // ---- load A tile (scatter to As[k][m]) ----
        {
            const float4 av = *(const float4*)(A + (size_t)(m0 + a_m) * K + k0 + a_k4);
            As[a_k4 + 0][a_m] = av.x;
            As[a_k4 + 1][a_m] = av.y;
            As[a_k4 + 2][a_m] = av.z;
            As[a_k4 + 3][a_m] = av.w;
        }
        // ---- load B tile into Bs[k][n] ----
        if (TRANSB) {
            const float4 bv = *(const float4*)(B + (size_t)(n0 + bt_n) * K + k0 + bt_k4);
            Bs[bt_k4 + 0][bt_n] = bv.x;
            Bs[bt_k4 + 1][bt_n] = bv.y;
            Bs[bt_k4 + 2][bt_n] = bv.z;
            Bs[bt_k4 + 3][bt_n] = bv.w;
        } else {
            const float4 bv = *(const float4*)(B + (size_t)(k0 + bn_k) * N + n0 + bn_n4);
            *(float4*)&Bs[bn_k][bn_n4] = bv;
        }
        __syncthreads();

#pragma unroll
        for (int k = 0; k < BK; ++k) {
            float a[8], b[8];
            *(float4*)(a)     = *(const float4*)&As[k][ty * 4];
            *(float4*)(a + 4) = *(const float4*)&As[k][ty * 4 + 64];
            *(float4*)(b)     = *(const float4*)&Bs[k][tx * 4];
            *(float4*)(b + 4) = *(const float4*)&Bs[k][tx * 4 + 64];
#pragma unroll
            for (int i = 0; i < 8; ++i)
#pragma unroll
                for (int j = 0; j < 8; ++j)
                    acc[i][j] = fmaf(a[i], b[j], acc[i][j]);
        }
        __syncthreads();
    }

    // ---- epilogue ----
#pragma unroll
    for (int i = 0; i < 8; ++i) {
        const int m = m0 + ty * 4 + (i & 3) + ((i >= 4) ? 64 : 0);
#pragma unroll
        for (int half = 0; half < 2; ++half) {
            const int n = n0 + tx * 4 + half * 64;
            float4 v;
            v.x = acc[i][half * 4 + 0];
            v.y = acc[i][half * 4 + 1];
            v.z = acc[i][half * 4 + 2];
            v.w = acc[i][half * 4 + 3];
            if (EPI >= 1) {
                const float4 bv = *(const float4*)(bias + n);
                v.x = fmaxf(v.x + bv.x, 0.f);
                v.y = fmaxf(v.y + bv.y, 0.f);
                v.z = fmaxf(v.z + bv.z, 0.f);
                v.w = fmaxf(v.w + bv.w, 0.f);
            }
            if (EPI == 2) {
                const float4 x1 = *(const float4*)(add1 + (size_t)m * N + n);
                const float4 x2 = *(const float4*)(add2 + (size_t)m * N + n);
                v.x += x1.x + x2.x;
                v.y += x1.y + x2.y;
                v.z += x1.z + x2.z;
                v.w += x1.w + x2.w;
            }
            *(float4*)(C + (size_t)m * N + n) = v;
        }
    }
}

// Causal row softmax, in-place. One block per row.
__global__ __launch_bounds__(256) void softmax_causal_kernel(float* __restrict__ S, int N)
{
    const int row = blockIdx.x;
    const int L   = row + 1;               // valid keys: 0..row
    float* s = S + (size_t)row * N;
    __shared__ float red[256];
    const int t = threadIdx.x;

    // max over [0, L)
    float m = -INFINITY;
    for (int j = t; j < L; j += 256) m = fmaxf(m, s[j]);
    red[t] = m;
    __syncthreads();
    for (int st = 128; st > 0; st >>= 1) {
        if (t < st) red[t] = fmaxf(red[t], red[t + st]);
        __syncthreads();
    }
    m = red[0];
    __syncthreads();

    // sum of exp
    float sum = 0.f;
    for (int j = t; j < L; j += 256) sum += expf(s[j] - m);
    red[t] = sum;
    __syncthreads();
    for (int st = 128; st > 0; st >>= 1) {
        if (t < st) red[t] += red[t + st];
        __syncthreads();
    }
    const float inv = 1.f / red[0];
    __syncthreads();

    // write probs; zero the masked region so P@x can use full K
    for (int j = t; j < N; j += 256)
        s[j] = (j < L) ? expf(s[j] - m) * inv : 0.f;
}

extern "C" void kernel_launch(void* const* d_in, const int* in_sizes, int n_in,
                              void* d_out, int out_size)
{
    const float* x        = (const float*)d_in[0];
    const float* qk       = (const float*)d_in[1];
    const float* ov       = (const float*)d_in[2];
    const float* w_up     = (const float*)d_in[3];
    const float* b_up     = (const float*)d_in[4];
    const float* w_hidden = (const float*)d_in[5];
    const float* b_hidden = (const float*)d_in[6];
    const float* w_down   = (const float*)d_in[7];
    const float* b_down   = (const float*)d_in[8];
    float* out = (float*)d_out;

    float *tmp1, *scores, *tmp2, *attn, *a1, *a2;
    cudaGetSymbolAddress((void**)&tmp1,   g_tmp1);
    cudaGetSymbolAddress((void**)&scores, g_scores);
    cudaGetSymbolAddress((void**)&tmp2,   g_tmp2);
    cudaGetSymbolAddress((void**)&attn,   g_attn);
    cudaGetSymbolAddress((void**)&a1,     g_a1);
    cudaGetSymbolAddress((void**)&a2,     g_a2);

    const dim3 blk(256);

    // 1) tmp1 = x @ qk                       [4096,2048]
    gemm_kernel<false, 0><<<dim3(D_MODEL / BN, N_CTX / BM), blk>>>(
        x, qk, tmp1, N_CTX, D_MODEL, D_MODEL, nullptr, nullptr, nullptr);

    // 2) scores = tmp1 @ x^T                 [4096,4096]
    gemm_kernel<true, 0><<<dim3(N_CTX / BN, N_CTX / BM), blk>>>(
        tmp1, x, scores, N_CTX, N_CTX, D_MODEL, nullptr, nullptr, nullptr);

    // 3) causal softmax (in-place, zero-fills masked region)
    softmax_causal_kernel<<<N_CTX, blk>>>(scores, N_CTX);

    // 4) tmp2 = P @ x                        [4096,2048]
    gemm_kernel<false, 0><<<dim3(D_MODEL / BN, N_CTX / BM), blk>>>(
        scores, x, tmp2, N_CTX, D_MODEL, N_CTX, nullptr, nullptr, nullptr);

    // 5) attn = tmp2 @ ov                    [4096,2048]
    gemm_kernel<false, 0><<<dim3(D_MODEL / BN, N_CTX / BM), blk>>>(
        tmp2, ov, attn, N_CTX, D_MODEL, D_MODEL, nullptr, nullptr, nullptr);

    // 6) a1 = relu(x @ w_up^T + b_up)        [4096,8192]
    gemm_kernel<true, 1><<<dim3(D_HIDDEN / BN, N_CTX / BM), blk>>>(
        x, w_up, a1, N_CTX, D_HIDDEN, D_MODEL, b_up, nullptr, nullptr);

    // 7) a2 = relu(a1 @ w_hidden^T + b_hid)  [4096,8192]
    gemm_kernel<true, 1><<<dim3(D_HIDDEN / BN, N_CTX / BM), blk>>>(
        a1, w_hidden, a2, N_CTX, D_HIDDEN, D_HIDDEN, b_hidden, nullptr, nullptr);

    // 8) out = x + attn + relu(a2 @ w_down^T + b_down)   [4096,2048]
    gemm_kernel<true, 2><<<dim3(D_MODEL / BN, N_CTX / BM), blk>>>(
        a2, w_down, out, N_CTX, D_MODEL, D_HIDDEN, b_down, x, attn);
}

// round 2
// speedup vs baseline: 1.1925x; 1.1925x over previous
#include <cuda_runtime.h>
#include <mma.h>
#include <math.h>

using namespace nvcuda;

// ---------------------------------------------------------------------------
// TransformerBlock on tensor pipe (wmma tf32).
//   Attention GEMMs: 3-term tf32 split (fp32-grade precision; softmax logits
//   must be accurate to <<1 absolute).
//   MLP GEMMs: single tf32 (error ~3e-5 of output norm).
// ---------------------------------------------------------------------------

#define N_CTX    4096
#define D_MODEL  2048
#define D_HIDDEN 8192

#define BM 128
#define BN 128
#define BK 16
#define BKP 20      // As leading dim (pad: 20*4B rows keep 16B alignment)
#define BNP 136     // Bs leading dim

// Scratch
__device__ float g_tmp1[(size_t)N_CTX * D_MODEL];
__device__ float g_scores[(size_t)N_CTX * N_CTX];
__device__ float g_tmp2[(size_t)N_CTX * D_MODEL];
__device__ float g_attn[(size_t)N_CTX * D_MODEL];
__device__ float g_a1[(size_t)N_CTX * D_HIDDEN];
__device__ float g_a2[(size_t)N_CTX * D_HIDDEN];

__device__ __forceinline__ float tf32r(float v) { return wmma::__float_to_tf32(v); }

// EPI: 0 plain, 1 relu(acc+bias), 2 add1+add2+relu(acc+bias)
template <bool TRANSB, int EPI, bool SPLIT>
__global__ __launch_bounds__(256) void tgemm(
    const float* __restrict__ A,
    const float* __restrict__ B,
    float* __restrict__ C,
    int M, int N, int K,
    const float* __restrict__ bias,
    const float* __restrict__ add1,
    const float* __restrict__ add2)
{
    __shared__ float AsHi[BM * BKP];
    __shared__ float BsHi[BK * BNP];
    __shared__ float AsLo[SPLIT ? BM * BKP : 1];
    __shared__ float BsLo[SPLIT ? BK * BNP : 1];
    __shared__ float ebuf[8][256];

    const int tid    = threadIdx.x;
    const int wid    = tid >> 5;
    const int lane   = tid & 31;
    const int warp_m = wid >> 2;     // 0..1 -> 64-row slab
    const int warp_n = wid & 3;      // 0..3 -> 32-col slab
    const int m0 = blockIdx.y * BM;
    const int n0 = blockIdx.x * BN;

    wmma::fragment<wmma::accumulator, 16, 16, 8, float> acc[4][2];
#pragma unroll
    for (int i = 0; i < 4; ++i)
#pragma unroll
        for (int j = 0; j < 2; ++j) wmma::fill_fragment(acc[i][j], 0.f);

    for (int k0 = 0; k0 < K; k0 += BK) {
        // ---- A tile: 128 x 16, stored [m][k] (tf32-rounded; lo = residual) ----
#pragma unroll
        for (int i = 0; i < 2; ++i) {
            const int idx = tid + i * 256;
            const int r = idx >> 2, c4 = (idx & 3) << 2;
            const float4 v = *(const float4*)(A + (size_t)(m0 + r) * K + k0 + c4);
            float4 h = make_float4(tf32r(v.x), tf32r(v.y), tf32r(v.z), tf32r(v.w));
            *(float4*)&AsHi[r * BKP + c4] = h;
            if (SPLIT) {
                float4 l = make_float4(tf32r(v.x - h.x), tf32r(v.y - h.y),
                                       tf32r(v.z - h.z), tf32r(v.w - h.w));
                *(float4*)&AsLo[r * BKP + c4] = l;
            }
        }
        // ---- B tile into [k][n] ----
        if (TRANSB) {
#pragma unroll
            for (int i = 0; i < 2; ++i) {
                const int idx = tid + i * 256;
                const int r = idx >> 2, c4 = (idx & 3) << 2;   // r = n, c4 = k
                const float4 v = *(const float4*)(B + (size_t)(n0 + r) * K + k0 + c4);
                BsHi[(c4 + 0) * BNP + r] = tf32r(v.x);
                BsHi[(c4 + 1) * BNP + r] = tf32r(v.y);
                BsHi[(c4 + 2) * BNP + r] = tf32r(v.z);
                BsHi[(c4 + 3) * BNP + r] = tf32r(v.w);
                if (SPLIT) {
                    BsLo[(c4 + 0) * BNP + r] = tf32r(v.x - tf32r(v.x));
                    BsLo[(c4 + 1) * BNP + r] = tf32r(v.y - tf32r(v.y));
                    BsLo[(c4 + 2) * BNP + r] = tf32r(v.z - tf32r(v.z));
                    BsLo[(c4 + 3) * BNP + r] = tf32r(v.w - tf32r(v.w));
                }
            }
        } else {
#pragma unroll
            for (int i = 0; i < 2; ++i) {
                const int idx = tid + i * 256;
                const int k = idx >> 5, n4 = (idx & 31) << 2;
                const float4 v = *(const float4*)(B + (size_t)(k0 + k) * N + n0 + n4);
                float4 h = make_float4(tf32r(v.x), tf32r(v.y), tf32r(v.z), tf32r(v.w));
                *(float4*)&BsHi[k * BNP + n4] = h;
                if (SPLIT) {
                    float4 l = make_float4(tf32r(v.x - h.x), tf32r(v.y - h.y),
                                           tf32r(v.z - h.z), tf32r(v.w - h.w));
                    *(float4*)&BsLo[k * BNP + n4] = l;
                }
            }
        }
        __syncthreads();

#pragma unroll
        for (int kk = 0; kk < BK; kk += 8) {
            wmma::fragment<wmma::matrix_b, 16, 16, 8, wmma::precision::tf32, wmma::row_major> bf[2], bfl[2];
#pragma unroll
            for (int ni = 0; ni < 2; ++ni) {
                wmma::load_matrix_sync(bf[ni], &BsHi[kk * BNP + warp_n * 32 + ni * 16], BNP);
                if (SPLIT)
                    wmma::load_matrix_sync(bfl[ni], &BsLo[kk * BNP + warp_n * 32 + ni * 16], BNP);
            }
#pragma unroll
            for (int mi = 0; mi < 4; ++mi) {
                wmma::fragment<wmma::matrix_a, 16, 16, 8, wmma::precision::tf32, wmma::row_major> af, afl;
                wmma::load_matrix_sync(af, &AsHi[(warp_m * 64 + mi * 16) * BKP + kk], BKP);
                if (SPLIT)
                    wmma::load_matrix_sync(afl, &AsLo[(warp_m * 64 + mi * 16) * BKP + kk], BKP);
#pragma unroll
                for (int ni = 0; ni < 2; ++ni) {
                    wmma::mma_sync(acc[mi][ni], af, bf[ni], acc[mi][ni]);
                    if (SPLIT) {
                        wmma::mma_sync(acc[mi][ni], af,  bfl[ni], acc[mi][ni]);
                        wmma::mma_sync(acc[mi][ni], afl, bf[ni],  acc[mi][ni]);
                    }
                }
            }
        }
        __syncthreads();
    }

    // ---- epilogue: spill each 16x16 frag through smem, apply ops, store ----
#pragma unroll
    for (int mi = 0; mi < 4; ++mi) {
#pragma unroll
        for (int ni = 0; ni < 2; ++ni) {
            wmma::store_matrix_sync(&ebuf[wid][0], acc[mi][ni], 16, wmma::mem_row_major);
            __syncwarp();
            const int r = lane >> 1;
            const int c = (lane & 1) * 8;
            const int m = m0 + warp_m * 64 + mi * 16 + r;
            const int n = n0 + warp_n * 32 + ni * 16 + c;
#pragma unroll
            for (int h = 0; h < 2; ++h) {
                float4 v = *(float4*)&ebuf[wid][r * 16 + c + h * 4];
                const int nn = n + h * 4;
                if (EPI >= 1) {
                    const float4 bv = *(const float4*)(bias + nn);
                    v.x = fmaxf(v.x + bv.x, 0.f);
                    v.y = fmaxf(v.y + bv.y, 0.f);
                    v.z = fmaxf(v.z + bv.z, 0.f);
                    v.w = fmaxf(v.w + bv.w, 0.f);
                }
                if (EPI == 2) {
                    const float4 x1 = *(const float4*)(add1 + (size_t)m * N + nn);
                    const float4 x2 = *(const float4*)(add2 + (size_t)m * N + nn);
                    v.x += x1.x + x2.x; v.y += x1.y + x2.y;
                    v.z += x1.z + x2.z; v.w += x1.w + x2.w;
                }
                *(float4*)(C + (size_t)m * N + nn) = v;
            }
            __syncwarp();
        }
    }
}

// Causal row softmax, in-place. One block per row.
__global__ __launch_bounds__(256) void softmax_causal_kernel(float* __restrict__ S, int N)
{
    const int row = blockIdx.x;
    const int L   = row + 1;
    float* s = S + (size_t)row * N;
    __shared__ float red[256];
    const int t = threadIdx.x;

    float m = -INFINITY;
    for (int j = t; j < L; j += 256) m = fmaxf(m, s[j]);
    red[t] = m;
    __syncthreads();
    for (int st = 128; st > 0; st >>= 1) {
        if (t < st) red[t] = fmaxf(red[t], red[t + st]);
        __syncthreads();
    }
    m = red[0];
    __syncthreads();

    float sum = 0.f;
    for (int j = t; j < L; j += 256) sum += expf(s[j] - m);
    red[t] = sum;
    __syncthreads();
    for (int st = 128; st > 0; st >>= 1) {
        if (t < st) red[t] += red[t + st];
        __syncthreads();
    }
    const float inv = 1.f / red[0];
    __syncthreads();

    for (int j = t; j < N; j += 256)
        s[j] = (j < L) ? expf(s[j] - m) * inv : 0.f;
}

extern "C" void kernel_launch(void* const* d_in, const int* in_sizes, int n_in,
                              void* d_out, int out_size)
{
    const float* x        = (const float*)d_in[0];
    const float* qk       = (const float*)d_in[1];
    const float* ov       = (const float*)d_in[2];
    const float* w_up     = (const float*)d_in[3];
    const float* b_up     = (const float*)d_in[4];
    const float* w_hidden = (const float*)d_in[5];
    const float* b_hidden = (const float*)d_in[6];
    const float* w_down   = (const float*)d_in[7];
    const float* b_down   = (const float*)d_in[8];
    float* out = (float*)d_out;

    float *tmp1, *scores, *tmp2, *attn, *a1, *a2;
    cudaGetSymbolAddress((void**)&tmp1,   g_tmp1);
    cudaGetSymbolAddress((void**)&scores, g_scores);
    cudaGetSymbolAddress((void**)&tmp2,   g_tmp2);
    cudaGetSymbolAddress((void**)&attn,   g_attn);
    cudaGetSymbolAddress((void**)&a1,     g_a1);
    cudaGetSymbolAddress((void**)&a2,     g_a2);

    const dim3 blk(256);

    // 1) tmp1 = x @ qk           (split tf32: feeds logits)
    tgemm<false, 0, true><<<dim3(D_MODEL / BN, N_CTX / BM), blk>>>(
        x, qk, tmp1, N_CTX, D_MODEL, D_MODEL, nullptr, nullptr, nullptr);

    // 2) scores = tmp1 @ x^T     (split tf32: logits need abs err << 1)
    tgemm<true, 0, true><<<dim3(N_CTX / BN, N_CTX / BM), blk>>>(
        tmp1, x, scores, N_CTX, N_CTX, D_MODEL, nullptr, nullptr, nullptr);

    // 3) causal softmax
    softmax_causal_kernel<<<N_CTX, blk>>>(scores, N_CTX);

    // 4) tmp2 = P @ x            (split tf32: probs feed 26x-amplifying @ov)
    tgemm<false, 0, true><<<dim3(D_MODEL / BN, N_CTX / BM), blk>>>(
        scores, x, tmp2, N_CTX, D_MODEL, N_CTX, nullptr, nullptr, nullptr);

    // 5) attn = tmp2 @ ov        (split tf32)
    tgemm<false, 0, true><<<dim3(D_MODEL / BN, N_CTX / BM), blk>>>(
        tmp2, ov, attn, N_CTX, D_MODEL, D_MODEL, nullptr, nullptr, nullptr);

    // 6) a1 = relu(x @ w_up^T + b_up)            (single tf32)
    tgemm<true, 1, false><<<dim3(D_HIDDEN / BN, N_CTX / BM), blk>>>(
        x, w_up, a1, N_CTX, D_HIDDEN, D_MODEL, b_up, nullptr, nullptr);

    // 7) a2 = relu(a1 @ w_hidden^T + b_hidden)   (single tf32)
    tgemm<true, 1, false><<<dim3(D_HIDDEN / BN, N_CTX / BM), blk>>>(
        a1, w_hidden, a2, N_CTX, D_HIDDEN, D_HIDDEN, b_hidden, nullptr, nullptr);

    // 8) out = x + attn + relu(a2 @ w_down^T + b_down)
    tgemm<true, 2, false><<<dim3(D_MODEL / BN, N_CTX / BM), blk>>>(
        a2, w_down, out, N_CTX, D_MODEL, D_HIDDEN, b_down, x, attn);
}

// round 5
// speedup vs baseline: 2.5581x; 2.1451x over previous
#include <cuda_runtime.h>
#include <cuda_bf16.h>
#include <math.h>
#include <stdint.h>

// ===========================================================================
// TransformerBlock via legacy tensor path (mma.sync.m16n8k16 bf16, fp32 acc).
// Build target is compute_103 (non-'a'), so tcgen05/TMEM is unavailable;
// sm_80-class mma.sync + ldmatrix + cp.async is the fastest reachable pipe.
// All GEMMs: 3-term bf16 split (AhBh + AhBl + AlBh)  -> ~fp24 effective.
// ===========================================================================

#define N_CTX    4096
#define D_MODEL  2048
#define D_HIDDEN 8192

#define BM 128
#define BN 128
#define BK 32
#define PITCH 80            // bytes per 32-bf16 row (64B data + 16B pad)
#define TILE_B (128 * PITCH)         // 10240 B, one operand tile
#define STAGE_B (4 * TILE_B)         // Ah, Al, Bh, Bl
#define NSTAGE 4
#define SMEM_TOTAL (NSTAGE * STAGE_B)   // 163840

// ------------------------- PTX helpers -------------------------------------
__device__ __forceinline__ uint32_t smem_u32(const void* p) {
    uint32_t a;
    asm("{ .reg .u64 t; cvta.to.shared.u64 t, %1; cvt.u32.u64 %0, t; }"
        : "=r"(a) : "l"(p));
    return a;
}
#define CP16(dst, src) \
    asm volatile("cp.async.cg.shared.global [%0], [%1], 16;" :: "r"(dst), "l"(src))
#define CP_COMMIT() asm volatile("cp.async.commit_group;")
#define CP_WAIT2()  asm volatile("cp.async.wait_group 2;")
#define CP_WAIT0()  asm volatile("cp.async.wait_group 0;")

#define LDSM4(r0, r1, r2, r3, addr) \
    asm volatile("ldmatrix.sync.aligned.m8n8.x4.shared.b16 {%0,%1,%2,%3}, [%4];" \
                 : "=r"(r0), "=r"(r1), "=r"(r2), "=r"(r3) : "r"(addr))

#define MMA(acc, a0, a1, a2, a3, b0, b1) \
    asm volatile("mma.sync.aligned.m16n8k16.row.col.f32.bf16.bf16.f32 " \
                 "{%0,%1,%2,%3},{%4,%5,%6,%7},{%8,%9},{%0,%1,%2,%3};" \
                 : "+f"((acc)[0]), "+f"((acc)[1]), "+f"((acc)[2]), "+f"((acc)[3]) \
                 : "r"(a0), "r"(a1), "r"(a2), "r"(a3), "r"(b0), "r"(b1))

// ------------------------- scratch -----------------------------------------
__device__ __nv_bfloat16 g_xhi[(size_t)N_CTX*D_MODEL],  g_xlo[(size_t)N_CTX*D_MODEL];
__device__ __nv_bfloat16 g_xThi[(size_t)D_MODEL*N_CTX], g_xTlo[(size_t)D_MODEL*N_CTX];
__device__ __nv_bfloat16 g_qkThi[(size_t)D_MODEL*D_MODEL], g_qkTlo[(size_t)D_MODEL*D_MODEL];
__device__ __nv_bfloat16 g_ovThi[(size_t)D_MODEL*D_MODEL], g_ovTlo[(size_t)D_MODEL*D_MODEL];
__device__ __nv_bfloat16 g_wuphi[(size_t)D_HIDDEN*D_MODEL], g_wuplo[(size_t)D_HIDDEN*D_MODEL];
__device__ __nv_bfloat16 g_whhi[(size_t)D_HIDDEN*D_HIDDEN], g_whlo[(size_t)D_HIDDEN*D_HIDDEN];
__device__ __nv_bfloat16 g_wdhi[(size_t)D_MODEL*D_HIDDEN], g_wdlo[(size_t)D_MODEL*D_HIDDEN];
__device__ __nv_bfloat16 g_t1hi[(size_t)N_CTX*D_MODEL],  g_t1lo[(size_t)N_CTX*D_MODEL];
__device__ __nv_bfloat16 g_Phi[(size_t)N_CTX*N_CTX],     g_Plo[(size_t)N_CTX*N_CTX];
__device__ __nv_bfloat16 g_t2hi[(size_t)N_CTX*D_MODEL],  g_t2lo[(size_t)N_CTX*D_MODEL];
__device__ __nv_bfloat16 g_a1hi[(size_t)N_CTX*D_HIDDEN], g_a1lo[(size_t)N_CTX*D_HIDDEN];
__device__ __nv_bfloat16 g_a2hi[(size_t)N_CTX*D_HIDDEN], g_a2lo[(size_t)N_CTX*D_HIDDEN];
__device__ float g_scores[(size_t)N_CTX*N_CTX];
__device__ float g_attn[(size_t)N_CTX*D_MODEL];

// ------------------------- GEMM --------------------------------------------
// C[M,N] = A[M,K] @ B^T  where B is stored [N,K] row-major (bf16 hi/lo pairs).
// EPI: 0 = bf16 pair out; 1 = f32 out; 2 = relu(acc+bias) -> bf16 pair;
//      3 = add1 + add2 + relu(acc+bias) -> f32
template <int EPI>
__global__ __launch_bounds__(256) void hgemm(
    const __nv_bfloat16* __restrict__ Ahi, const __nv_bfloat16* __restrict__ Alo,
    const __nv_bfloat16* __restrict__ Bhi, const __nv_bfloat16* __restrict__ Blo,
    int M, int N, int K,
    float* __restrict__ Cf,
    __nv_bfloat16* __restrict__ Chi, __nv_bfloat16* __restrict__ Clo,
    const float* __restrict__ bias,
    const float* __restrict__ add1, const float* __restrict__ add2)
{
    extern __shared__ char sm[];
    const uint32_t sbase = smem_u32(sm);

    const int tid  = threadIdx.x;
    const int lane = tid & 31;
    const int wid  = tid >> 5;
    const int wm   = wid & 1;          // 0/1 : 64-row slab
    const int wn   = wid >> 1;         // 0..3: 32-col slab
    const int m0   = blockIdx.x * BM;
    const int n0   = blockIdx.y * BN;
    const int T    = K / BK;

    // per-thread loader decomposition: 8 x 16B chunks per stage
    int l_tile[8], l_r[8], l_c[8];
#pragma unroll
    for (int i = 0; i < 8; ++i) {
        const int idx = tid + i * 256;
        l_tile[i] = idx >> 9;
        l_r[i]    = (idx >> 2) & 127;
        l_c[i]    = idx & 3;
    }

    auto issue_stage = [&](int t, int s) {
        const int k0 = t * BK;
        const uint32_t sb = sbase + (uint32_t)s * STAGE_B;
#pragma unroll
        for (int i = 0; i < 8; ++i) {
            const int tile = l_tile[i], r = l_r[i], c = l_c[i];
            const uint32_t dst = sb + (uint32_t)tile * TILE_B + (uint32_t)(r * PITCH + c * 16);
            const __nv_bfloat16* src;
            if      (tile == 0) src = Ahi + (size_t)(m0 + r) * K + k0 + c * 8;
            else if (tile == 1) src = Alo + (size_t)(m0 + r) * K + k0 + c * 8;
            else if (tile == 2) src = Bhi + (size_t)(n0 + r) * K + k0 + c * 8;
            else                src = Blo + (size_t)(n0 + r) * K + k0 + c * 8;
            CP16(dst, src);
        }
        CP_COMMIT();
    };

    float acc[4][4][4];
#pragma unroll
    for (int a = 0; a < 4; ++a)
#pragma unroll
        for (int b = 0; b < 4; ++b)
#pragma unroll
            for (int c = 0; c < 4; ++c) acc[a][b][c] = 0.f;

    issue_stage(0, 0);
    issue_stage(1, 1);
    issue_stage(2, 2);

    // precomputed fragment smem offsets (within a stage)
    const uint32_t a_row  = (uint32_t)(wm * 64 + (lane & 15));
    const uint32_t a_koff = (uint32_t)((lane >> 4) << 4);
    const uint32_t b_row  = (uint32_t)(wn * 32 + (lane & 7) + (((lane >> 4) & 1) << 3));
    const uint32_t b_koff = (uint32_t)(((lane >> 3) & 1) << 4);

    for (int t = 0; t < T; ++t) {
        const int s = t & 3;
        CP_WAIT2();
        __syncthreads();
        const uint32_t sb = sbase + (uint32_t)s * STAGE_B;

#pragma unroll
        for (int ks = 0; ks < 2; ++ks) {
            uint32_t ah[4][4], al[4][4], bh[2][4], bl[2][4];
#pragma unroll
            for (int mi = 0; mi < 4; ++mi) {
                const uint32_t a = sb + (a_row + mi * 16) * PITCH + ks * 32 + a_koff;
                LDSM4(ah[mi][0], ah[mi][1], ah[mi][2], ah[mi][3], a);
                LDSM4(al[mi][0], al[mi][1], al[mi][2], al[mi][3], a + TILE_B);
            }
#pragma unroll
            for (int np = 0; np < 2; ++np) {
                const uint32_t b = sb + 2 * TILE_B + (b_row + np * 16) * PITCH + ks * 32 + b_koff;
                LDSM4(bh[np][0], bh[np][1], bh[np][2], bh[np][3], b);
                LDSM4(bl[np][0], bl[np][1], bl[np][2], bl[np][3], b + TILE_B);
            }
#pragma unroll
            for (int mi = 0; mi < 4; ++mi)
#pragma unroll
                for (int ni = 0; ni < 4; ++ni) {
                    const int np = ni >> 1, o = (ni & 1) * 2;
                    MMA(acc[mi][ni], ah[mi][0], ah[mi][1], ah[mi][2], ah[mi][3],
                        bh[np][o], bh[np][o + 1]);
                    MMA(acc[mi][ni], ah[mi][0], ah[mi][1], ah[mi][2], ah[mi][3],
                        bl[np][o], bl[np][o + 1]);
                    MMA(acc[mi][ni], al[mi][0], al[mi][1], al[mi][2], al[mi][3],
                        bh[np][o], bh[np][o + 1]);
                }
        }
        if (t + 3 < T) issue_stage(t + 3, (t + 3) & 3);
        else           CP_COMMIT();
    }

    // ---- epilogue (direct from registers) ----
    const int rl = lane >> 2;          // 0..7
    const int cl = (lane & 3) * 2;     // even
#pragma unroll
    for (int mi = 0; mi < 4; ++mi)
#pragma unroll
        for (int ni = 0; ni < 4; ++ni) {
            const int mA = m0 + wm * 64 + mi * 16 + rl;
            const int n  = n0 + wn * 32 + ni * 8 + cl;
#pragma unroll
            for (int h = 0; h < 2; ++h) {
                const int m = mA + h * 8;
                float vx = acc[mi][ni][h * 2 + 0];
                float vy = acc[mi][ni][h * 2 + 1];
                if (EPI == 2 || EPI == 3) {
                    vx = fmaxf(vx + bias[n],     0.f);
                    vy = fmaxf(vy + bias[n + 1], 0.f);
                }
                if (EPI == 3) {
                    const float2 x1 = *(const float2*)(add1 + (size_t)m * N + n);
                    const float2 x2 = *(const float2*)(add2 + (size_t)m * N + n);
                    vx += x1.x + x2.x;
                    vy += x1.y + x2.y;
                }
                if (EPI == 1 || EPI == 3) {
                    float2 v = make_float2(vx, vy);
                    *(float2*)(Cf + (size_t)m * N + n) = v;
                } else {
                    __nv_bfloat162 H, L;
                    H.x = __float2bfloat16(vx);
                    H.y = __float2bfloat16(vy);
                    L.x = __float2bfloat16(vx - __bfloat162float(H.x));
                    L.y = __float2bfloat16(vy - __bfloat162float(H.y));
                    *(__nv_bfloat162*)(Chi + (size_t)m * N + n) = H;
                    *(__nv_bfloat162*)(Clo + (size_t)m * N + n) = L;
                }
            }
        }
    CP_WAIT0();
}

// ------------------------- conversions --------------------------------------
__global__ __launch_bounds__(256) void cvt_pair(const float* __restrict__ in,
                                                __nv_bfloat16* __restrict__ hi,
                                                __nv_bfloat16* __restrict__ lo,
                                                size_t n4)
{
    for (size_t i = (size_t)blockIdx.x * 256 + threadIdx.x; i < n4;
         i += (size_t)gridDim.x * 256) {
        const float4 v = ((const float4*)in)[i];
        union { __nv_bfloat16 b[4]; uint2 u; } H, L;
        const float vv[4] = {v.x, v.y, v.z, v.w};
#pragma unroll
        for (int k = 0; k < 4; ++k) {
            H.b[k] = __float2bfloat16(vv[k]);
            L.b[k] = __float2bfloat16(vv[k] - __bfloat162float(H.b[k]));
        }
        ((uint2*)hi)[i] = H.u;
        ((uint2*)lo)[i] = L.u;
    }
}

// out[C,R] = in[R,C]^T (bf16 pair)
__global__ __launch_bounds__(256) void cvt_pair_T(const float* __restrict__ in,
                                                  int R, int C,
                                                  __nv_bfloat16* __restrict__ hi,
                                                  __nv_bfloat16* __restrict__ lo)
{
    __shared__ float ts[32][33];
    const int x0 = blockIdx.x * 32, y0 = blockIdx.y * 32;
    const int tx = threadIdx.x, ty = threadIdx.y;
#pragma unroll
    for (int j = 0; j < 32; j += 8)
        ts[ty + j][tx] = in[(size_t)(y0 + ty + j) * C + x0 + tx];
    __syncthreads();
#pragma unroll
    for (int j = 0; j < 32; j += 8) {
        const float v = ts[tx][ty + j];
        const __nv_bfloat16 h = __float2bfloat16(v);
        const size_t o = (size_t)(x0 + ty + j) * R + y0 + tx;
        hi[o] = h;
        lo[o] = __float2bfloat16(v - __bfloat162float(h));
    }
}

// ------------------------- softmax ------------------------------------------
__global__ __launch_bounds__(256) void softmax_causal(const float* __restrict__ S,
                                                      __nv_bfloat16* __restrict__ Phi,
                                                      __nv_bfloat16* __restrict__ Plo,
                                                      int N)
{
    const int row = blockIdx.x;
    const int L = row + 1;
    const float* s = S + (size_t)row * N;
    __shared__ float red[256];
    const int t = threadIdx.x;

    float m = -INFINITY;
    for (int j = t; j < L; j += 256) m = fmaxf(m, s[j]);
    red[t] = m; __syncthreads();
    for (int st = 128; st > 0; st >>= 1) {
        if (t < st) red[t] = fmaxf(red[t], red[t + st]);
        __syncthreads();
    }
    m = red[0]; __syncthreads();

    float sum = 0.f;
    for (int j = t; j < L; j += 256) sum += expf(s[j] - m);
    red[t] = sum; __syncthreads();
    for (int st = 128; st > 0; st >>= 1) {
        if (t < st) red[t] += red[t + st];
        __syncthreads();
    }
    const float inv = 1.f / red[0]; __syncthreads();

    __nv_bfloat16* ph = Phi + (size_t)row * N;
    __nv_bfloat16* pl = Plo + (size_t)row * N;
    for (int j = t; j < N; j += 256) {
        const float p = (j < L) ? expf(s[j] - m) * inv : 0.f;
        const __nv_bfloat16 h = __float2bfloat16(p);
        ph[j] = h;
        pl[j] = __float2bfloat16(p - __bfloat162float(h));
    }
}

// ------------------------- launch -------------------------------------------
static inline void* sym(const void* s) { void* p; cudaGetSymbolAddress(&p, s); return p; }

extern "C" void kernel_launch(void* const* d_in, const int* in_sizes, int n_in,
                              void* d_out, int out_size)
{
    const float* x        = (const float*)d_in[0];
    const float* qk       = (const float*)d_in[1];
    const float* ov       = (const float*)d_in[2];
    const float* w_up     = (const float*)d_in[3];
    const float* b_up     = (const float*)d_in[4];
    const float* w_hidden = (const float*)d_in[5];
    const float* b_hidden = (const float*)d_in[6];
    const float* w_down   = (const float*)d_in[7];
    const float* b_down   = (const float*)d_in[8];
    float* out = (float*)d_out;

    static bool attr_done = false;
    if (!attr_done) {
        cudaFuncSetAttribute(hgemm<0>, cudaFuncAttributeMaxDynamicSharedMemorySize, SMEM_TOTAL);
        cudaFuncSetAttribute(hgemm<1>, cudaFuncAttributeMaxDynamicSharedMemorySize, SMEM_TOTAL);
        cudaFuncSetAttribute(hgemm<2>, cudaFuncAttributeMaxDynamicSharedMemorySize, SMEM_TOTAL);
        cudaFuncSetAttribute(hgemm<3>, cudaFuncAttributeMaxDynamicSharedMemorySize, SMEM_TOTAL);
        attr_done = true;
    }

    __nv_bfloat16 *xhi = (__nv_bfloat16*)sym(g_xhi),   *xlo = (__nv_bfloat16*)sym(g_xlo);
    __nv_bfloat16 *xThi = (__nv_bfloat16*)sym(g_xThi), *xTlo = (__nv_bfloat16*)sym(g_xTlo);
    __nv_bfloat16 *qkThi = (__nv_bfloat16*)sym(g_qkThi), *qkTlo = (__nv_bfloat16*)sym(g_qkTlo);
    __nv_bfloat16 *ovThi = (__nv_bfloat16*)sym(g_ovThi), *ovTlo = (__nv_bfloat16*)sym(g_ovTlo);
    __nv_bfloat16 *wuphi = (__nv_bfloat16*)sym(g_wuphi), *wuplo = (__nv_bfloat16*)sym(g_wuplo);
    __nv_bfloat16 *whhi = (__nv_bfloat16*)sym(g_whhi),  *whlo = (__nv_bfloat16*)sym(g_whlo);
    __nv_bfloat16 *wdhi = (__nv_bfloat16*)sym(g_wdhi),  *wdlo = (__nv_bfloat16*)sym(g_wdlo);
    __nv_bfloat16 *t1hi = (__nv_bfloat16*)sym(g_t1hi),  *t1lo = (__nv_bfloat16*)sym(g_t1lo);
    __nv_bfloat16 *Phi = (__nv_bfloat16*)sym(g_Phi),    *Plo = (__nv_bfloat16*)sym(g_Plo);
    __nv_bfloat16 *t2hi = (__nv_bfloat16*)sym(g_t2hi),  *t2lo = (__nv_bfloat16*)sym(g_t2lo);
    __nv_bfloat16 *a1hi = (__nv_bfloat16*)sym(g_a1hi),  *a1lo = (__nv_bfloat16*)sym(g_a1lo);
    __nv_bfloat16 *a2hi = (__nv_bfloat16*)sym(g_a2hi),  *a2lo = (__nv_bfloat16*)sym(g_a2lo);
    float *scores = (float*)sym(g_scores);
    float *attn   = (float*)sym(g_attn);

    // conversions (inputs -> bf16 hi/lo; B operands stored [N,K])
    cvt_pair<<<4096, 256>>>(x, xhi, xlo, (size_t)N_CTX * D_MODEL / 4);
    cvt_pair_T<<<dim3(D_MODEL/32, N_CTX/32), dim3(32,8)>>>(x, N_CTX, D_MODEL, xThi, xTlo);
    cvt_pair_T<<<dim3(D_MODEL/32, D_MODEL/32), dim3(32,8)>>>(qk, D_MODEL, D_MODEL, qkThi, qkTlo);
    cvt_pair_T<<<dim3(D_MODEL/32, D_MODEL/32), dim3(32,8)>>>(ov, D_MODEL, D_MODEL, ovThi, ovTlo);
    cvt_pair<<<4096, 256>>>(w_up, wuphi, wuplo, (size_t)D_HIDDEN * D_MODEL / 4);
    cvt_pair<<<8192, 256>>>(w_hidden, whhi, whlo, (size_t)D_HIDDEN * D_HIDDEN / 4);
    cvt_pair<<<4096, 256>>>(w_down, wdhi, wdlo, (size_t)D_MODEL * D_HIDDEN / 4);

    // 1) t1 = x @ qk
    hgemm<0><<<dim3(N_CTX/BM, D_MODEL/BN), 256, SMEM_TOTAL>>>(
        xhi, xlo, qkThi, qkTlo, N_CTX, D_MODEL, D_MODEL,
        nullptr, t1hi, t1lo, nullptr, nullptr, nullptr);
    // 2) scores = t1 @ x^T
    hgemm<1><<<dim3(N_CTX/BM, N_CTX/BN), 256, SMEM_TOTAL>>>(
        t1hi, t1lo, xhi, xlo, N_CTX, N_CTX, D_MODEL,
        scores, nullptr, nullptr, nullptr, nullptr, nullptr);
    // 3) causal softmax -> P (bf16 pair)
    softmax_causal<<<N_CTX, 256>>>(scores, Phi, Plo, N_CTX);
    // 4) t2 = P @ x
    hgemm<0><<<dim3(N_CTX/BM, D_MODEL/BN), 256, SMEM_TOTAL>>>(
        Phi, Plo, xThi, xTlo, N_CTX, D_MODEL, N_CTX,
        nullptr, t2hi, t2lo, nullptr, nullptr, nullptr);
    // 5) attn = t2 @ ov
    hgemm<1><<<dim3(N_CTX/BM, D_MODEL/BN), 256, SMEM_TOTAL>>>(
        t2hi, t2lo, ovThi, ovTlo, N_CTX, D_MODEL, D_MODEL,
        attn, nullptr, nullptr, nullptr, nullptr, nullptr);
    // 6) a1 = relu(x @ w_up^T + b_up)
    hgemm<2><<<dim3(N_CTX/BM, D_HIDDEN/BN), 256, SMEM_TOTAL>>>(
        xhi, xlo, wuphi, wuplo, N_CTX, D_HIDDEN, D_MODEL,
        nullptr, a1hi, a1lo, b_up, nullptr, nullptr);
    // 7) a2 = relu(a1 @ w_hidden^T + b_hidden)
    hgemm<2><<<dim3(N_CTX/BM, D_HIDDEN/BN), 256, SMEM_TOTAL>>>(
        a1hi, a1lo, whhi, whlo, N_CTX, D_HIDDEN, D_HIDDEN,
        nullptr, a2hi, a2lo, b_hidden, nullptr, nullptr);
    // 8) out = x + attn + relu(a2 @ w_down^T + b_down)
    hgemm<3><<<dim3(N_CTX/BM, D_MODEL/BN), 256, SMEM_TOTAL>>>(
        a2hi, a2lo, wdhi, wdlo, N_CTX, D_MODEL, D_HIDDEN,
        out, nullptr, nullptr, b_down, x, attn);
}

// round 6
// speedup vs baseline: 2.7252x; 1.0653x over previous
#include <cuda_runtime.h>
#include <cuda_bf16.h>
#include <math.h>
#include <stdint.h>

// ===========================================================================
// TransformerBlock, legacy tensor path (mma.sync.m16n8k16 bf16, fp32 acc).
// 3-term bf16 split everywhere. R6: 64x64 warp tiles (CTA 128x256, 3-stage
// cp.async pipeline) + causal block-skip / K-trim in the attention GEMMs.
// ===========================================================================

#define N_CTX    4096
#define D_MODEL  2048
#define D_HIDDEN 8192

#define BM 128
#define BN 256
#define BK 32
#define PITCH 80                 // bytes per 32-bf16 row (64B data + 16B pad)
#define AH_OFF 0
#define AL_OFF (128 * PITCH)     // 10240
#define BH_OFF (2 * 128 * PITCH) // 20480
#define BL_OFF (BH_OFF + 256 * PITCH)
#define STAGE_B (BL_OFF + 256 * PITCH)   // 61440
#define NSTAGE 3
#define SMEM_TOTAL (NSTAGE * STAGE_B)    // 184320

// ------------------------- PTX helpers -------------------------------------
__device__ __forceinline__ uint32_t smem_u32(const void* p) {
    uint32_t a;
    asm("{ .reg .u64 t; cvta.to.shared.u64 t, %1; cvt.u32.u64 %0, t; }"
        : "=r"(a) : "l"(p));
    return a;
}
#define CP16(dst, src) \
    asm volatile("cp.async.cg.shared.global [%0], [%1], 16;" :: "r"(dst), "l"(src))
#define CP_COMMIT() asm volatile("cp.async.commit_group;")
#define CP_WAIT2()  asm volatile("cp.async.wait_group 2;")
#define CP_WAIT0()  asm volatile("cp.async.wait_group 0;")

#define LDSM4(r0, r1, r2, r3, addr) \
    asm volatile("ldmatrix.sync.aligned.m8n8.x4.shared.b16 {%0,%1,%2,%3}, [%4];" \
                 : "=r"(r0), "=r"(r1), "=r"(r2), "=r"(r3) : "r"(addr))

#define MMA(acc, a0, a1, a2, a3, b0, b1) \
    asm volatile("mma.sync.aligned.m16n8k16.row.col.f32.bf16.bf16.f32 " \
                 "{%0,%1,%2,%3},{%4,%5,%6,%7},{%8,%9},{%0,%1,%2,%3};" \
                 : "+f"((acc)[0]), "+f"((acc)[1]), "+f"((acc)[2]), "+f"((acc)[3]) \
                 : "r"(a0), "r"(a1), "r"(a2), "r"(a3), "r"(b0), "r"(b1))

// ------------------------- scratch -----------------------------------------
__device__ __nv_bfloat16 g_xhi[(size_t)N_CTX*D_MODEL],  g_xlo[(size_t)N_CTX*D_MODEL];
__device__ __nv_bfloat16 g_xThi[(size_t)D_MODEL*N_CTX], g_xTlo[(size_t)D_MODEL*N_CTX];
__device__ __nv_bfloat16 g_qkThi[(size_t)D_MODEL*D_MODEL], g_qkTlo[(size_t)D_MODEL*D_MODEL];
__device__ __nv_bfloat16 g_ovThi[(size_t)D_MODEL*D_MODEL], g_ovTlo[(size_t)D_MODEL*D_MODEL];
__device__ __nv_bfloat16 g_wuphi[(size_t)D_HIDDEN*D_MODEL], g_wuplo[(size_t)D_HIDDEN*D_MODEL];
__device__ __nv_bfloat16 g_whhi[(size_t)D_HIDDEN*D_HIDDEN], g_whlo[(size_t)D_HIDDEN*D_HIDDEN];
__device__ __nv_bfloat16 g_wdhi[(size_t)D_MODEL*D_HIDDEN], g_wdlo[(size_t)D_MODEL*D_HIDDEN];
__device__ __nv_bfloat16 g_t1hi[(size_t)N_CTX*D_MODEL],  g_t1lo[(size_t)N_CTX*D_MODEL];
__device__ __nv_bfloat16 g_Phi[(size_t)N_CTX*N_CTX],     g_Plo[(size_t)N_CTX*N_CTX];
__device__ __nv_bfloat16 g_t2hi[(size_t)N_CTX*D_MODEL],  g_t2lo[(size_t)N_CTX*D_MODEL];
__device__ __nv_bfloat16 g_a1hi[(size_t)N_CTX*D_HIDDEN], g_a1lo[(size_t)N_CTX*D_HIDDEN];
__device__ __nv_bfloat16 g_a2hi[(size_t)N_CTX*D_HIDDEN], g_a2lo[(size_t)N_CTX*D_HIDDEN];
__device__ float g_scores[(size_t)N_CTX*N_CTX];
__device__ float g_attn[(size_t)N_CTX*D_MODEL];

// ------------------------- GEMM --------------------------------------------
// C[M,N] = A[M,K] @ B^T,  B stored [N,K] row-major (bf16 hi/lo pairs).
// EPI: 0 = bf16 pair; 1 = f32; 2 = relu(acc+bias)->bf16 pair;
//      3 = add1+add2+relu(acc+bias)->f32
// CAUSAL: 0 none; 1 skip blocks entirely above diagonal (scores);
//         2 trim K to m0+BM (A = P, strictly causal rows)
template <int EPI, int CAUSAL>
__global__ __launch_bounds__(256) void hgemm(
    const __nv_bfloat16* __restrict__ Ahi, const __nv_bfloat16* __restrict__ Alo,
    const __nv_bfloat16* __restrict__ Bhi, const __nv_bfloat16* __restrict__ Blo,
    int M, int N, int K,
    float* __restrict__ Cf,
    __nv_bfloat16* __restrict__ Chi, __nv_bfloat16* __restrict__ Clo,
    const float* __restrict__ bias,
    const float* __restrict__ add1, const float* __restrict__ add2)
{
    const int m0 = blockIdx.x * BM;
    const int n0 = blockIdx.y * BN;
    if (CAUSAL == 1 && n0 >= m0 + BM) return;   // softmax never reads there

    extern __shared__ char sm[];
    const uint32_t sbase = smem_u32(sm);

    const int tid  = threadIdx.x;
    const int lane = tid & 31;
    const int wid  = tid >> 5;
    const int wm   = wid & 1;          // 0/1 : 64-row slab
    const int wn   = wid >> 1;         // 0..3: 64-col slab
    const int T    = (CAUSAL == 2) ? ((m0 + BM) / BK) : (K / BK);

    auto issue_stage = [&](int t, int s) {
        const int k0 = t * BK;
        const uint32_t sb = sbase + (uint32_t)s * STAGE_B;
#pragma unroll
        for (int i = 0; i < 12; ++i) {
            const int idx = tid + i * 256;       // 0..3071
            uint32_t dst;
            const __nv_bfloat16* src;
            if (idx < 1024) {                    // A hi/lo: 128 rows x 4 chunks
                const int lo = idx >> 9;         // 0=hi 1=lo
                const int r  = (idx >> 2) & 127;
                const int c  = idx & 3;
                dst = sb + (lo ? AL_OFF : AH_OFF) + (uint32_t)(r * PITCH + c * 16);
                src = (lo ? Alo : Ahi) + (size_t)(m0 + r) * K + k0 + c * 8;
            } else {                             // B hi/lo: 256 rows x 4 chunks
                const int j  = idx - 1024;
                const int lo = j >> 10;
                const int r  = (j >> 2) & 255;
                const int c  = j & 3;
                dst = sb + (lo ? BL_OFF : BH_OFF) + (uint32_t)(r * PITCH + c * 16);
                src = (lo ? Blo : Bhi) + (size_t)(n0 + r) * K + k0 + c * 8;
            }
            CP16(dst, src);
        }
        CP_COMMIT();
    };

    float acc[4][8][4];
#pragma unroll
    for (int a = 0; a < 4; ++a)
#pragma unroll
        for (int b = 0; b < 8; ++b)
#pragma unroll
            for (int c = 0; c < 4; ++c) acc[a][b][c] = 0.f;

#pragma unroll
    for (int i = 0; i < NSTAGE; ++i) {
        if (i < T) issue_stage(i, i);
        else       CP_COMMIT();
    }

    const uint32_t a_row  = (uint32_t)(wm * 64 + (lane & 15));
    const uint32_t a_koff = (uint32_t)((lane >> 4) << 4);
    const uint32_t b_rbase = (uint32_t)(wn * 64 + (lane & 7) + (((lane >> 4) & 1) << 3));
    const uint32_t b_koff  = (uint32_t)(((lane >> 3) & 1) << 4);

    for (int t = 0; t < T; ++t) {
        const int s = t % NSTAGE;
        CP_WAIT2();
        __syncthreads();
        const uint32_t sb = sbase + (uint32_t)s * STAGE_B;

#pragma unroll
        for (int ks = 0; ks < 2; ++ks) {
            uint32_t ah[4][4], al[4][4];
#pragma unroll
            for (int mi = 0; mi < 4; ++mi) {
                const uint32_t a = sb + (a_row + mi * 16) * PITCH + ks * 32 + a_koff;
                LDSM4(ah[mi][0], ah[mi][1], ah[mi][2], ah[mi][3], a + AH_OFF);
                LDSM4(al[mi][0], al[mi][1], al[mi][2], al[mi][3], a + AL_OFF);
            }
#pragma unroll
            for (int np = 0; np < 4; ++np) {
                uint32_t bh[4], bl[4];
                const uint32_t b = sb + (b_rbase + np * 16) * PITCH + ks * 32 + b_koff;
                LDSM4(bh[0], bh[1], bh[2], bh[3], b + BH_OFF);
                LDSM4(bl[0], bl[1], bl[2], bl[3], b + BL_OFF);
#pragma unroll
                for (int mi = 0; mi < 4; ++mi)
#pragma unroll
                    for (int half = 0; half < 2; ++half) {
                        float* ac = acc[mi][np * 2 + half];
                        const int o = half * 2;
                        MMA(ac, ah[mi][0], ah[mi][1], ah[mi][2], ah[mi][3],
                            bh[o], bh[o + 1]);
                        MMA(ac, ah[mi][0], ah[mi][1], ah[mi][2], ah[mi][3],
                            bl[o], bl[o + 1]);
                        MMA(ac, al[mi][0], al[mi][1], al[mi][2], al[mi][3],
                            bh[o], bh[o + 1]);
                    }
            }
        }
        __syncthreads();
        if (t + NSTAGE < T) issue_stage(t + NSTAGE, (t + NSTAGE) % NSTAGE);
        else                CP_COMMIT();
    }

    // ---- epilogue (direct from registers) ----
    const int rl = lane >> 2;
    const int cl = (lane & 3) * 2;
#pragma unroll
    for (int mi = 0; mi < 4; ++mi)
#pragma unroll
        for (int ni = 0; ni < 8; ++ni) {
            const int mA = m0 + wm * 64 + mi * 16 + rl;
            const int n  = n0 + wn * 64 + ni * 8 + cl;
#pragma unroll
            for (int h = 0; h < 2; ++h) {
                const int m = mA + h * 8;
                float vx = acc[mi][ni][h * 2 + 0];
                float vy = acc[mi][ni][h * 2 + 1];
                if (EPI == 2 || EPI == 3) {
                    vx = fmaxf(vx + bias[n],     0.f);
                    vy = fmaxf(vy + bias[n + 1], 0.f);
                }
                if (EPI == 3) {
                    const float2 x1 = *(const float2*)(add1 + (size_t)m * N + n);
                    const float2 x2 = *(const float2*)(add2 + (size_t)m * N + n);
                    vx += x1.x + x2.x;
                    vy += x1.y + x2.y;
                }
                if (EPI == 1 || EPI == 3) {
                    *(float2*)(Cf + (size_t)m * N + n) = make_float2(vx, vy);
                } else {
                    __nv_bfloat162 H, L;
                    H.x = __float2bfloat16(vx);
                    H.y = __float2bfloat16(vy);
                    L.x = __float2bfloat16(vx - __bfloat162float(H.x));
                    L.y = __float2bfloat16(vy - __bfloat162float(H.y));
                    *(__nv_bfloat162*)(Chi + (size_t)m * N + n) = H;
                    *(__nv_bfloat162*)(Clo + (size_t)m * N + n) = L;
                }
            }
        }
    CP_WAIT0();
}

// ------------------------- conversions --------------------------------------
__global__ __launch_bounds__(256) void cvt_pair(const float* __restrict__ in,
                                                __nv_bfloat16* __restrict__ hi,
                                                __nv_bfloat16* __restrict__ lo,
                                                size_t n4)
{
    for (size_t i = (size_t)blockIdx.x * 256 + threadIdx.x; i < n4;
         i += (size_t)gridDim.x * 256) {
        const float4 v = ((const float4*)in)[i];
        union { __nv_bfloat16 b[4]; uint2 u; } H, L;
        const float vv[4] = {v.x, v.y, v.z, v.w};
#pragma unroll
        for (int k = 0; k < 4; ++k) {
            H.b[k] = __float2bfloat16(vv[k]);
            L.b[k] = __float2bfloat16(vv[k] - __bfloat162float(H.b[k]));
        }
        ((uint2*)hi)[i] = H.u;
        ((uint2*)lo)[i] = L.u;
    }
}

__global__ __launch_bounds__(256) void cvt_pair_T(const float* __restrict__ in,
                                                  int R, int C,
                                                  __nv_bfloat16* __restrict__ hi,
                                                  __nv_bfloat16* __restrict__ lo)
{
    __shared__ float ts[32][33];
    const int x0 = blockIdx.x * 32, y0 = blockIdx.y * 32;
    const int tx = threadIdx.x, ty = threadIdx.y;
#pragma unroll
    for (int j = 0; j < 32; j += 8)
        ts[ty + j][tx] = in[(size_t)(y0 + ty + j) * C + x0 + tx];
    __syncthreads();
#pragma unroll
    for (int j = 0; j < 32; j += 8) {
        const float v = ts[tx][ty + j];
        const __nv_bfloat16 h = __float2bfloat16(v);
        const size_t o = (size_t)(x0 + ty + j) * R + y0 + tx;
        hi[o] = h;
        lo[o] = __float2bfloat16(v - __bfloat162float(h));
    }
}

// ------------------------- softmax ------------------------------------------
__global__ __launch_bounds__(256) void softmax_causal(const float* __restrict__ S,
                                                      __nv_bfloat16* __restrict__ Phi,
                                                      __nv_bfloat16* __restrict__ Plo,
                                                      int N)
{
    const int row = blockIdx.x;
    const int L = row + 1;
    const float* s = S + (size_t)row * N;
    __shared__ float red[256];
    const int t = threadIdx.x;

    float m = -INFINITY;
    for (int j = t; j < L; j += 256) m = fmaxf(m, s[j]);
    red[t] = m; __syncthreads();
    for (int st = 128; st > 0; st >>= 1) {
        if (t < st) red[t] = fmaxf(red[t], red[t + st]);
        __syncthreads();
    }
    m = red[0]; __syncthreads();

    float sum = 0.f;
    for (int j = t; j < L; j += 256) sum += expf(s[j] - m);
    red[t] = sum; __syncthreads();
    for (int st = 128; st > 0; st >>= 1) {
        if (t < st) red[t] += red[t + st];
        __syncthreads();
    }
    const float inv = 1.f / red[0]; __syncthreads();

    __nv_bfloat16* ph = Phi + (size_t)row * N;
    __nv_bfloat16* pl = Plo + (size_t)row * N;
    for (int j = t; j < N; j += 256) {
        const float p = (j < L) ? expf(s[j] - m) * inv : 0.f;
        const __nv_bfloat16 h = __float2bfloat16(p);
        ph[j] = h;
        pl[j] = __float2bfloat16(p - __bfloat162float(h));
    }
}

// ------------------------- launch -------------------------------------------
static inline void* sym(const void* s) { void* p; cudaGetSymbolAddress(&p, s); return p; }

extern "C" void kernel_launch(void* const* d_in, const int* in_sizes, int n_in,
                              void* d_out, int out_size)
{
    const float* x        = (const float*)d_in[0];
    const float* qk       = (const float*)d_in[1];
    const float* ov       = (const float*)d_in[2];
    const float* w_up     = (const float*)d_in[3];
    const float* b_up     = (const float*)d_in[4];
    const float* w_hidden = (const float*)d_in[5];
    const float* b_hidden = (const float*)d_in[6];
    const float* w_down   = (const float*)d_in[7];
    const float* b_down   = (const float*)d_in[8];
    float* out = (float*)d_out;

    static bool attr_done = false;
    if (!attr_done) {
        cudaFuncSetAttribute(hgemm<0,0>, cudaFuncAttributeMaxDynamicSharedMemorySize, SMEM_TOTAL);
        cudaFuncSetAttribute(hgemm<1,1>, cudaFuncAttributeMaxDynamicSharedMemorySize, SMEM_TOTAL);
        cudaFuncSetAttribute(hgemm<0,2>, cudaFuncAttributeMaxDynamicSharedMemorySize, SMEM_TOTAL);
        cudaFuncSetAttribute(hgemm<1,0>, cudaFuncAttributeMaxDynamicSharedMemorySize, SMEM_TOTAL);
        cudaFuncSetAttribute(hgemm<2,0>, cudaFuncAttributeMaxDynamicSharedMemorySize, SMEM_TOTAL);
        cudaFuncSetAttribute(hgemm<3,0>, cudaFuncAttributeMaxDynamicSharedMemorySize, SMEM_TOTAL);
        attr_done = true;
    }

    __nv_bfloat16 *xhi = (__nv_bfloat16*)sym(g_xhi),   *xlo = (__nv_bfloat16*)sym(g_xlo);
    __nv_bfloat16 *xThi = (__nv_bfloat16*)sym(g_xThi), *xTlo = (__nv_bfloat16*)sym(g_xTlo);
    __nv_bfloat16 *qkThi = (__nv_bfloat16*)sym(g_qkThi), *qkTlo = (__nv_bfloat16*)sym(g_qkTlo);
    __nv_bfloat16 *ovThi = (__nv_bfloat16*)sym(g_ovThi), *ovTlo = (__nv_bfloat16*)sym(g_ovTlo);
    __nv_bfloat16 *wuphi = (__nv_bfloat16*)sym(g_wuphi), *wuplo = (__nv_bfloat16*)sym(g_wuplo);
    __nv_bfloat16 *whhi = (__nv_bfloat16*)sym(g_whhi),  *whlo = (__nv_bfloat16*)sym(g_whlo);
    __nv_bfloat16 *wdhi = (__nv_bfloat16*)sym(g_wdhi),  *wdlo = (__nv_bfloat16*)sym(g_wdlo);
    __nv_bfloat16 *t1hi = (__nv_bfloat16*)sym(g_t1hi),  *t1lo = (__nv_bfloat16*)sym(g_t1lo);
    __nv_bfloat16 *Phi = (__nv_bfloat16*)sym(g_Phi),    *Plo = (__nv_bfloat16*)sym(g_Plo);
    __nv_bfloat16 *t2hi = (__nv_bfloat16*)sym(g_t2hi),  *t2lo = (__nv_bfloat16*)sym(g_t2lo);
    __nv_bfloat16 *a1hi = (__nv_bfloat16*)sym(g_a1hi),  *a1lo = (__nv_bfloat16*)sym(g_a1lo);
    __nv_bfloat16 *a2hi = (__nv_bfloat16*)sym(g_a2hi),  *a2lo = (__nv_bfloat16*)sym(g_a2lo);
    float *scores = (float*)sym(g_scores);
    float *attn   = (float*)sym(g_attn);

    cvt_pair<<<4096, 256>>>(x, xhi, xlo, (size_t)N_CTX * D_MODEL / 4);
    cvt_pair_T<<<dim3(D_MODEL/32, N_CTX/32), dim3(32,8)>>>(x, N_CTX, D_MODEL, xThi, xTlo);
    cvt_pair_T<<<dim3(D_MODEL/32, D_MODEL/32), dim3(32,8)>>>(qk, D_MODEL, D_MODEL, qkThi, qkTlo);
    cvt_pair_T<<<dim3(D_MODEL/32, D_MODEL/32), dim3(32,8)>>>(ov, D_MODEL, D_MODEL, ovThi, ovTlo);
    cvt_pair<<<4096, 256>>>(w_up, wuphi, wuplo, (size_t)D_HIDDEN * D_MODEL / 4);
    cvt_pair<<<8192, 256>>>(w_hidden, whhi, whlo, (size_t)D_HIDDEN * D_HIDDEN / 4);
    cvt_pair<<<4096, 256>>>(w_down, wdhi, wdlo, (size_t)D_MODEL * D_HIDDEN / 4);

    // 1) t1 = x @ qk
    hgemm<0,0><<<dim3(N_CTX/BM, D_MODEL/BN), 256, SMEM_TOTAL>>>(
        xhi, xlo, qkThi, qkTlo, N_CTX, D_MODEL, D_MODEL,
        nullptr, t1hi, t1lo, nullptr, nullptr, nullptr);
    // 2) scores = t1 @ x^T  (skip fully-masked blocks)
    hgemm<1,1><<<dim3(N_CTX/BM, N_CTX/BN), 256, SMEM_TOTAL>>>(
        t1hi, t1lo, xhi, xlo, N_CTX, N_CTX, D_MODEL,
        scores, nullptr, nullptr, nullptr, nullptr, nullptr);
    // 3) causal softmax -> P (bf16 pair)
    softmax_causal<<<N_CTX, 256>>>(scores, Phi, Plo, N_CTX);
    // 4) t2 = P @ x  (K trimmed to m0+BM)
    hgemm<0,2><<<dim3(N_CTX/BM, D_MODEL/BN), 256, SMEM_TOTAL>>>(
        Phi, Plo, xThi, xTlo, N_CTX, D_MODEL, N_CTX,
        nullptr, t2hi, t2lo, nullptr, nullptr, nullptr);
    // 5) attn = t2 @ ov
    hgemm<1,0><<<dim3(N_CTX/BM, D_MODEL/BN), 256, SMEM_TOTAL>>>(
        t2hi, t2lo, ovThi, ovTlo, N_CTX, D_MODEL, D_MODEL,
        attn, nullptr, nullptr, nullptr, nullptr, nullptr);
    // 6) a1 = relu(x @ w_up^T + b_up)
    hgemm<2,0><<<dim3(N_CTX/BM, D_HIDDEN/BN), 256, SMEM_TOTAL>>>(
        xhi, xlo, wuphi, wuplo, N_CTX, D_HIDDEN, D_MODEL,
        nullptr, a1hi, a1lo, b_up, nullptr, nullptr);
    // 7) a2 = relu(a1 @ w_hidden^T + b_hidden)
    hgemm<2,0><<<dim3(N_CTX/BM, D_HIDDEN/BN), 256, SMEM_TOTAL>>>(
        a1hi, a1lo, whhi, whlo, N_CTX, D_HIDDEN, D_HIDDEN,
        nullptr, a2hi, a2lo, b_hidden, nullptr, nullptr);
    // 8) out = x + attn + relu(a2 @ w_down^T + b_down)
    hgemm<3,0><<<dim3(N_CTX/BM, D_MODEL/BN), 256, SMEM_TOTAL>>>(
        a2hi, a2lo, wdhi, wdlo, N_CTX, D_MODEL, D_HIDDEN,
        out, nullptr, nullptr, b_down, x, attn);
}